// round 4
// baseline (speedup 1.0000x reference)
#include <cuda_runtime.h>
#include <math.h>

#define BB 256
#define QQ 300
#define GG 16
#define KMAX 10   // ceil(QQ/32) columns per lane

// ---------------- device scratch (no allocations allowed) ----------------
__device__ double g_l1[BB];               // per-batch selected-cost sum
__device__ int    g_cnt[BB];              // per-batch nval

__constant__ float c_tw[32] = {
    1.17236407f, 1.0166286f, 1.19620973f, 0.5544405f, 0.63531401f, 0.51258428f,
    1.08866652f, 1.15795989f, 1.07389395f, 0.98728399f, 1.12754142f, 1.05953744f,
    1.16945323f, 1.15512349f, 1.02097204f, 1.15795989f, 1.07147279f, 0.50627649f,
    1.07147279f, 0.61697221f, 1.16367678f, 1.0231585f, 1.18416106f, 1.04329092f,
    1.10645159f, 1.18416106f, 1.15795989f, 1.16367678f, 0.73949534f, 0.78760821f,
    1.08617476f, 1.00805777f
};

// ---------------- fused kernel: cost tile (all 4 warps) + Hungarian (warp 0) ----
__global__ __launch_bounds__(128) void fused_kernel(
    const float* __restrict__ ph,
    const float* __restrict__ pr,
    const float* __restrict__ pt,
    const int* __restrict__ iid,
    const int* __restrict__ vid,
    const int* __restrict__ tgt,
    const int* __restrict__ mask)
{
    const int b   = blockIdx.x;
    const int tid = threadIdx.x;

    __shared__ float C[GG][QQ];           // cost[g][q], row-contiguous in q
    __shared__ float s_u[GG + 1];
    __shared__ int   s_p[QQ + 1];
    __shared__ int   s_way[QQ + 1];
    __shared__ int   si[GG], sv[GG], st[GG];

    if (tid < GG) {
        si[tid] = iid[b * GG + tid];
        sv[tid] = vid[b * GG + tid];
        st[tid] = tgt[b * GG + tid];
    }
    for (int j = tid; j <= QQ; j += 128) { s_p[j] = 0; s_way[j] = 0; }
    if (tid <= GG) s_u[tid] = 0.f;
    __syncthreads();

    // ---- phase 1: cost matrix into shared ----
    for (int q = tid; q < QQ; q += 128) {
        float h[9], r[13], t[2];
        const float* hp = ph + (size_t)(b * QQ + q) * 9;
        const float* rp = pr + (size_t)(b * QQ + q) * 13;
        const float* tp = pt + (size_t)(b * QQ + q) * 2;

        float mh = -INFINITY, mr = -INFINITY, mt = -INFINITY;
#pragma unroll
        for (int i = 0; i < 9; i++)  { h[i] = hp[i]; mh = fmaxf(mh, h[i]); }
#pragma unroll
        for (int i = 0; i < 13; i++) { r[i] = rp[i]; mr = fmaxf(mr, r[i]); }
#pragma unroll
        for (int i = 0; i < 2; i++)  { t[i] = tp[i]; mt = fmaxf(mt, t[i]); }

        float sh = 0.f, sr = 0.f, stt = 0.f;
#pragma unroll
        for (int i = 0; i < 9; i++)  sh  += expf(h[i] - mh);
#pragma unroll
        for (int i = 0; i < 13; i++) sr  += expf(r[i] - mr);
#pragma unroll
        for (int i = 0; i < 2; i++)  stt += expf(t[i] - mt);

        float lh = mh + logf(sh);
        float lr = mr + logf(sr);
        float lt = mt + logf(stt);

#pragma unroll
        for (int g = 0; g < GG; g++) {
            C[g][q] = (lh - h[si[g]]) + (lr - r[sv[g]]) + (lt - t[st[g]]);
        }
    }
    __syncthreads();

    // ---- phase 2: warp 0 runs JV Hungarian ----
    if (tid >= 32) return;
    const int lane = tid;

    unsigned mb = __ballot_sync(0xffffffffu, lane < GG && mask[b * GG + lane] != 0);
    const int n = __popc(mb);

    float v[KMAX], minv[KMAX];
#pragma unroll
    for (int k = 0; k < KMAX; k++) v[k] = 0.f;

    for (int i = 1; i <= n; i++) {
#pragma unroll
        for (int k = 0; k < KMAX; k++) minv[k] = INFINITY;
        unsigned used = 0;
        int j0 = 0;
        if (lane == 0) s_p[0] = i;
        __syncwarp();

        while (true) {
            // mark j0 used (lane that owns it sets its bit); column 0 handled by the
            // unconditional u[i] += delta below (p[0] == i while this row searches).
            if (j0 > 0 && (((j0 - 1) & 31) == lane))
                used |= 1u << ((j0 - 1) >> 5);

            const int   i0   = s_p[j0];
            const float u_i0 = s_u[i0];
            const float* Crow = &C[i0 - 1][0];

            float best = INFINITY;
            int   bidx = QQ + 2;
#pragma unroll
            for (int k = 0; k < KMAX; k++) {
                int j = 1 + lane + 32 * k;
                if (j <= QQ && !((used >> k) & 1u)) {
                    float cur = Crow[j - 1] - u_i0 - v[k];
                    if (cur < minv[k]) { minv[k] = cur; s_way[j] = j0; }
                    if (minv[k] < best) { best = minv[k]; bidx = j; }  // k ascending => lowest j wins ties
                }
            }
            // warp argmin, lowest index wins ties (matches np.argmin)
#pragma unroll
            for (int off = 16; off > 0; off >>= 1) {
                float ov = __shfl_down_sync(0xffffffffu, best, off);
                int   oi = __shfl_down_sync(0xffffffffu, bidx, off);
                if (ov < best || (ov == best && oi < bidx)) { best = ov; bidx = oi; }
            }
            const float delta = __shfl_sync(0xffffffffu, best, 0);
            const int   j1    = __shfl_sync(0xffffffffu, bidx, 0);

            // potentials update
#pragma unroll
            for (int k = 0; k < KMAX; k++) {
                int j = 1 + lane + 32 * k;
                if (j <= QQ) {
                    if ((used >> k) & 1u) {
                        v[k] -= delta;
                        s_u[s_p[j]] += delta;     // distinct p[j] across used cols
                    } else {
                        minv[k] -= delta;
                    }
                }
            }
            if (lane == 0) s_u[i] += delta;       // virtual column 0 (p[0] = i)
            __syncwarp();

            if (s_p[j1] == 0) { j0 = j1; break; }
            j0 = j1;
        }

        // augment alternating path (serial, tiny)
        if (lane == 0) {
            int jj = j0;
            while (jj) {
                int jp = s_way[jj];
                s_p[jj] = s_p[jp];
                jj = jp;
            }
        }
        __syncwarp();
    }

    // sum selected float32 costs
    double local = 0.0;
#pragma unroll
    for (int k = 0; k < KMAX; k++) {
        int j = 1 + lane + 32 * k;
        if (j <= QQ) {
            int pj = s_p[j];
            if (pj > 0) local += (double)C[pj - 1][j - 1];
        }
    }
#pragma unroll
    for (int off = 16; off > 0; off >>= 1)
        local += __shfl_down_sync(0xffffffffu, local, off);
    if (lane == 0) { g_l1[b] = local; g_cnt[b] = n; }
}

// ---------------- kernel 2: BCE + final combine ----------------
__global__ void final_kernel(const float* __restrict__ IVT,
                             const int* __restrict__ triplet,
                             float* __restrict__ out) {
    const int tid = threadIdx.x;
    __shared__ double r1[256], r2[256], r3[256];

    double l1 = 0.0, cnt = 0.0;
    for (int b = tid; b < BB; b += 256) { l1 += g_l1[b]; cnt += (double)g_cnt[b]; }

    double bce = 0.0;
    for (int i = tid; i < BB * 32; i += 256) {
        float x = IVT[i];
        float t = (float)triplet[i];
        float v = fmaxf(x, 0.f) - x * t + log1pf(expf(-fabsf(x)));
        bce += (double)(c_tw[i & 31] * v);
    }
    r1[tid] = l1; r2[tid] = cnt; r3[tid] = bce;
    __syncthreads();
    for (int s = 128; s > 0; s >>= 1) {
        if (tid < s) { r1[tid] += r1[tid + s]; r2[tid] += r2[tid + s]; r3[tid] += r3[tid + s]; }
        __syncthreads();
    }
    if (tid == 0) {
        double loss1 = r1[0] / r2[0];
        double loss5 = r3[0] / (double)(BB * 32);
        out[0] = (float)(0.1 * loss1 + 1.0 * loss5);
    }
}

// ---------------- launch ----------------
extern "C" void kernel_launch(void* const* d_in, const int* in_sizes, int n_in,
                              void* d_out, int out_size) {
    const float* pred_head = (const float*)d_in[0];
    const float* pred_rel  = (const float*)d_in[1];
    const float* pred_tail = (const float*)d_in[2];
    const float* IVT       = (const float*)d_in[3];
    const int*   iid       = (const int*)d_in[4];
    const int*   vid       = (const int*)d_in[5];
    const int*   tgt       = (const int*)d_in[6];
    // d_in[7..9] (instrument, verb, target) unused by the reference
    const int*   triplet   = (const int*)d_in[10];
    const int*   mask      = (const int*)d_in[11];
    float* out = (float*)d_out;

    fused_kernel<<<BB, 128>>>(pred_head, pred_rel, pred_tail, iid, vid, tgt, mask);
    final_kernel<<<1, 256>>>(IVT, triplet, out);
}

// round 5
// speedup vs baseline: 1.5157x; 1.5157x over previous
#include <cuda_runtime.h>
#include <math.h>

#define BB 256
#define QQ 300
#define GG 16
#define KMAX 10   // ceil(QQ/32) columns per lane

// ---------------- device scratch (no allocations allowed) ----------------
__device__ double g_l1[BB];               // per-batch selected-cost sum
__device__ int    g_cnt[BB];              // per-batch nval

__constant__ float c_tw[32] = {
    1.17236407f, 1.0166286f, 1.19620973f, 0.5544405f, 0.63531401f, 0.51258428f,
    1.08866652f, 1.15795989f, 1.07389395f, 0.98728399f, 1.12754142f, 1.05953744f,
    1.16945323f, 1.15512349f, 1.02097204f, 1.15795989f, 1.07147279f, 0.50627649f,
    1.07147279f, 0.61697221f, 1.16367678f, 1.0231585f, 1.18416106f, 1.04329092f,
    1.10645159f, 1.18416106f, 1.15795989f, 1.16367678f, 0.73949534f, 0.78760821f,
    1.08617476f, 1.00805777f
};

// ---------------- fused kernel: cost tile (all 4 warps) + Hungarian (warp 0) ----
__global__ __launch_bounds__(128) void fused_kernel(
    const float* __restrict__ ph,
    const float* __restrict__ pr,
    const float* __restrict__ pt,
    const int* __restrict__ iid,
    const int* __restrict__ vid,
    const int* __restrict__ tgt,
    const int* __restrict__ mask)
{
    const int b   = blockIdx.x;
    const int tid = threadIdx.x;

    __shared__ float C[GG][QQ];           // cost[g][q], row-contiguous in q
    __shared__ float s_u[GG + 1];
    __shared__ int   s_p[QQ + 1];
    __shared__ int   s_way[QQ + 1];
    __shared__ int   si[GG], sv[GG], st[GG];

    if (tid < GG) {
        si[tid] = iid[b * GG + tid];
        sv[tid] = vid[b * GG + tid];
        st[tid] = tgt[b * GG + tid];
    }
    for (int j = tid; j <= QQ; j += 128) { s_p[j] = 0; s_way[j] = 0; }
    if (tid <= GG) s_u[tid] = 0.f;
    __syncthreads();

    // ---- phase 1: cost matrix into shared ----
    for (int q = tid; q < QQ; q += 128) {
        float h[9], r[13], t[2];
        const float* hp = ph + (size_t)(b * QQ + q) * 9;
        const float* rp = pr + (size_t)(b * QQ + q) * 13;
        const float* tp = pt + (size_t)(b * QQ + q) * 2;

        float mh = -INFINITY, mr = -INFINITY, mt = -INFINITY;
#pragma unroll
        for (int i = 0; i < 9; i++)  { h[i] = hp[i]; mh = fmaxf(mh, h[i]); }
#pragma unroll
        for (int i = 0; i < 13; i++) { r[i] = rp[i]; mr = fmaxf(mr, r[i]); }
#pragma unroll
        for (int i = 0; i < 2; i++)  { t[i] = tp[i]; mt = fmaxf(mt, t[i]); }

        float sh = 0.f, sr = 0.f, stt = 0.f;
#pragma unroll
        for (int i = 0; i < 9; i++)  sh  += expf(h[i] - mh);
#pragma unroll
        for (int i = 0; i < 13; i++) sr  += expf(r[i] - mr);
#pragma unroll
        for (int i = 0; i < 2; i++)  stt += expf(t[i] - mt);

        float lh = mh + logf(sh);
        float lr = mr + logf(sr);
        float lt = mt + logf(stt);

#pragma unroll
        for (int g = 0; g < GG; g++) {
            C[g][q] = (lh - h[si[g]]) + (lr - r[sv[g]]) + (lt - t[st[g]]);
        }
    }
    __syncthreads();

    // ---- phase 2: warp 0 runs JV Hungarian ----
    if (tid >= 32) return;
    const int lane = tid;

    unsigned mb = __ballot_sync(0xffffffffu, lane < GG && mask[b * GG + lane] != 0);
    const int n = __popc(mb);

    float v[KMAX], minv[KMAX];
#pragma unroll
    for (int k = 0; k < KMAX; k++) v[k] = 0.f;

    for (int i = 1; i <= n; i++) {
#pragma unroll
        for (int k = 0; k < KMAX; k++) minv[k] = INFINITY;
        unsigned used = 0;
        int j0 = 0;
        if (lane == 0) s_p[0] = i;
        __syncwarp();

        while (true) {
            // mark j0 used (lane that owns it sets its bit); column 0 handled by the
            // unconditional u[i] += delta below (p[0] == i while this row searches).
            if (j0 > 0 && (((j0 - 1) & 31) == lane))
                used |= 1u << ((j0 - 1) >> 5);

            const int   i0   = s_p[j0];
            const float u_i0 = s_u[i0];
            const float* Crow = &C[i0 - 1][0];

            float best = INFINITY;
            int   bidx = QQ + 2;
#pragma unroll
            for (int k = 0; k < KMAX; k++) {
                int j = 1 + lane + 32 * k;
                if (j <= QQ && !((used >> k) & 1u)) {
                    float cur = Crow[j - 1] - u_i0 - v[k];
                    if (cur < minv[k]) { minv[k] = cur; s_way[j] = j0; }
                    if (minv[k] < best) { best = minv[k]; bidx = j; }  // k ascending => lowest j wins ties
                }
            }
            // warp argmin, lowest index wins ties (matches np.argmin)
#pragma unroll
            for (int off = 16; off > 0; off >>= 1) {
                float ov = __shfl_down_sync(0xffffffffu, best, off);
                int   oi = __shfl_down_sync(0xffffffffu, bidx, off);
                if (ov < best || (ov == best && oi < bidx)) { best = ov; bidx = oi; }
            }
            const float delta = __shfl_sync(0xffffffffu, best, 0);
            const int   j1    = __shfl_sync(0xffffffffu, bidx, 0);

            // potentials update
#pragma unroll
            for (int k = 0; k < KMAX; k++) {
                int j = 1 + lane + 32 * k;
                if (j <= QQ) {
                    if ((used >> k) & 1u) {
                        v[k] -= delta;
                        s_u[s_p[j]] += delta;     // distinct p[j] across used cols
                    } else {
                        minv[k] -= delta;
                    }
                }
            }
            if (lane == 0) s_u[i] += delta;       // virtual column 0 (p[0] = i)
            __syncwarp();

            if (s_p[j1] == 0) { j0 = j1; break; }
            j0 = j1;
        }

        // augment alternating path (serial, tiny)
        if (lane == 0) {
            int jj = j0;
            while (jj) {
                int jp = s_way[jj];
                s_p[jj] = s_p[jp];
                jj = jp;
            }
        }
        __syncwarp();
    }

    // sum selected float32 costs
    double local = 0.0;
#pragma unroll
    for (int k = 0; k < KMAX; k++) {
        int j = 1 + lane + 32 * k;
        if (j <= QQ) {
            int pj = s_p[j];
            if (pj > 0) local += (double)C[pj - 1][j - 1];
        }
    }
#pragma unroll
    for (int off = 16; off > 0; off >>= 1)
        local += __shfl_down_sync(0xffffffffu, local, off);
    if (lane == 0) { g_l1[b] = local; g_cnt[b] = n; }
}

// ---------------- kernel 2: BCE + final combine ----------------
__global__ void final_kernel(const float* __restrict__ IVT,
                             const int* __restrict__ triplet,
                             float* __restrict__ out) {
    const int tid = threadIdx.x;
    __shared__ double r1[256], r2[256], r3[256];

    double l1 = 0.0, cnt = 0.0;
    for (int b = tid; b < BB; b += 256) { l1 += g_l1[b]; cnt += (double)g_cnt[b]; }

    double bce = 0.0;
    for (int i = tid; i < BB * 32; i += 256) {
        float x = IVT[i];
        float t = (float)triplet[i];
        float v = fmaxf(x, 0.f) - x * t + log1pf(expf(-fabsf(x)));
        bce += (double)(c_tw[i & 31] * v);
    }
    r1[tid] = l1; r2[tid] = cnt; r3[tid] = bce;
    __syncthreads();
    for (int s = 128; s > 0; s >>= 1) {
        if (tid < s) { r1[tid] += r1[tid + s]; r2[tid] += r2[tid + s]; r3[tid] += r3[tid + s]; }
        __syncthreads();
    }
    if (tid == 0) {
        double loss1 = r1[0] / r2[0];
        double loss5 = r3[0] / (double)(BB * 32);
        out[0] = (float)(0.1 * loss1 + 1.0 * loss5);
    }
}

// ---------------- launch ----------------
extern "C" void kernel_launch(void* const* d_in, const int* in_sizes, int n_in,
                              void* d_out, int out_size) {
    const float* pred_head = (const float*)d_in[0];
    const float* pred_rel  = (const float*)d_in[1];
    const float* pred_tail = (const float*)d_in[2];
    const float* IVT       = (const float*)d_in[3];
    const int*   iid       = (const int*)d_in[4];
    const int*   vid       = (const int*)d_in[5];
    const int*   tgt       = (const int*)d_in[6];
    // d_in[7..9] (instrument, verb, target) unused by the reference
    const int*   triplet   = (const int*)d_in[10];
    const int*   mask      = (const int*)d_in[11];
    float* out = (float*)d_out;

    fused_kernel<<<BB, 128>>>(pred_head, pred_rel, pred_tail, iid, vid, tgt, mask);
    final_kernel<<<1, 256>>>(IVT, triplet, out);
}

// round 6
// speedup vs baseline: 1.5591x; 1.0286x over previous
#include <cuda_runtime.h>
#include <math.h>

#define BB 256
#define QQ 300
#define GG 16
#define KMAX 10   // ceil(QQ/32) columns per lane

// ---------------- device scratch (no allocations allowed) ----------------
__device__ double g_l1[BB];               // per-batch selected-cost sum
__device__ int    g_cnt[BB];              // per-batch nval

__constant__ float c_tw[32] = {
    1.17236407f, 1.0166286f, 1.19620973f, 0.5544405f, 0.63531401f, 0.51258428f,
    1.08866652f, 1.15795989f, 1.07389395f, 0.98728399f, 1.12754142f, 1.05953744f,
    1.16945323f, 1.15512349f, 1.02097204f, 1.15795989f, 1.07147279f, 0.50627649f,
    1.07147279f, 0.61697221f, 1.16367678f, 1.0231585f, 1.18416106f, 1.04329092f,
    1.10645159f, 1.18416106f, 1.15795989f, 1.16367678f, 0.73949534f, 0.78760821f,
    1.08617476f, 1.00805777f
};

// ---------------- fused kernel: cost tile (all 4 warps) + Hungarian (warp 0) ----
__global__ __launch_bounds__(128) void fused_kernel(
    const float* __restrict__ ph,
    const float* __restrict__ pr,
    const float* __restrict__ pt,
    const int* __restrict__ iid,
    const int* __restrict__ vid,
    const int* __restrict__ tgt,
    const int* __restrict__ mask)
{
    const int b   = blockIdx.x;
    const int tid = threadIdx.x;

    __shared__ float C[GG][QQ];           // cost[g][q], row-contiguous in q
    __shared__ float s_u[GG + 1];
    __shared__ int   s_p[QQ + 1];
    __shared__ int   s_way[QQ + 1];
    __shared__ int   si[GG], sv[GG], st[GG];

    if (tid < GG) {
        si[tid] = iid[b * GG + tid];
        sv[tid] = vid[b * GG + tid];
        st[tid] = tgt[b * GG + tid];
    }
    for (int j = tid; j <= QQ; j += 128) { s_p[j] = 0; s_way[j] = 0; }
    if (tid <= GG) s_u[tid] = 0.f;
    __syncthreads();

    // ---- phase 1: cost matrix into shared ----
    for (int q = tid; q < QQ; q += 128) {
        float h[9], r[13], t[2];
        const float* hp = ph + (size_t)(b * QQ + q) * 9;
        const float* rp = pr + (size_t)(b * QQ + q) * 13;
        const float* tp = pt + (size_t)(b * QQ + q) * 2;

        float mh = -INFINITY, mr = -INFINITY, mt = -INFINITY;
#pragma unroll
        for (int i = 0; i < 9; i++)  { h[i] = hp[i]; mh = fmaxf(mh, h[i]); }
#pragma unroll
        for (int i = 0; i < 13; i++) { r[i] = rp[i]; mr = fmaxf(mr, r[i]); }
#pragma unroll
        for (int i = 0; i < 2; i++)  { t[i] = tp[i]; mt = fmaxf(mt, t[i]); }

        float sh = 0.f, sr = 0.f, stt = 0.f;
#pragma unroll
        for (int i = 0; i < 9; i++)  sh  += expf(h[i] - mh);
#pragma unroll
        for (int i = 0; i < 13; i++) sr  += expf(r[i] - mr);
#pragma unroll
        for (int i = 0; i < 2; i++)  stt += expf(t[i] - mt);

        float lh = mh + logf(sh);
        float lr = mr + logf(sr);
        float lt = mt + logf(stt);

#pragma unroll
        for (int g = 0; g < GG; g++) {
            C[g][q] = (lh - h[si[g]]) + (lr - r[sv[g]]) + (lt - t[st[g]]);
        }
    }
    __syncthreads();

    // ---- phase 2: warp 0 runs JV Hungarian ----
    if (tid >= 32) return;
    const int lane = tid;

    unsigned mb = __ballot_sync(0xffffffffu, lane < GG && mask[b * GG + lane] != 0);
    const int n = __popc(mb);

    float v[KMAX], minv[KMAX];
#pragma unroll
    for (int k = 0; k < KMAX; k++) v[k] = 0.f;

    for (int i = 1; i <= n; i++) {
#pragma unroll
        for (int k = 0; k < KMAX; k++) minv[k] = INFINITY;
        unsigned used = 0;
        int j0 = 0;
        if (lane == 0) s_p[0] = i;
        __syncwarp();

        while (true) {
            // mark j0 used (lane that owns it sets its bit); column 0 handled by the
            // unconditional u[i] += delta below (p[0] == i while this row searches).
            if (j0 > 0 && (((j0 - 1) & 31) == lane))
                used |= 1u << ((j0 - 1) >> 5);

            const int   i0   = s_p[j0];
            const float u_i0 = s_u[i0];
            const float* Crow = &C[i0 - 1][0];

            float best = INFINITY;
            int   bidx = QQ + 2;
#pragma unroll
            for (int k = 0; k < KMAX; k++) {
                int j = 1 + lane + 32 * k;
                if (j <= QQ && !((used >> k) & 1u)) {
                    float cur = Crow[j - 1] - u_i0 - v[k];
                    if (cur < minv[k]) { minv[k] = cur; s_way[j] = j0; }
                    if (minv[k] < best) { best = minv[k]; bidx = j; }  // k ascending => lowest j wins ties
                }
            }
            // warp argmin, lowest index wins ties (matches np.argmin)
#pragma unroll
            for (int off = 16; off > 0; off >>= 1) {
                float ov = __shfl_down_sync(0xffffffffu, best, off);
                int   oi = __shfl_down_sync(0xffffffffu, bidx, off);
                if (ov < best || (ov == best && oi < bidx)) { best = ov; bidx = oi; }
            }
            const float delta = __shfl_sync(0xffffffffu, best, 0);
            const int   j1    = __shfl_sync(0xffffffffu, bidx, 0);

            // potentials update
#pragma unroll
            for (int k = 0; k < KMAX; k++) {
                int j = 1 + lane + 32 * k;
                if (j <= QQ) {
                    if ((used >> k) & 1u) {
                        v[k] -= delta;
                        s_u[s_p[j]] += delta;     // distinct p[j] across used cols
                    } else {
                        minv[k] -= delta;
                    }
                }
            }
            if (lane == 0) s_u[i] += delta;       // virtual column 0 (p[0] = i)
            __syncwarp();

            if (s_p[j1] == 0) { j0 = j1; break; }
            j0 = j1;
        }

        // augment alternating path (serial, tiny)
        if (lane == 0) {
            int jj = j0;
            while (jj) {
                int jp = s_way[jj];
                s_p[jj] = s_p[jp];
                jj = jp;
            }
        }
        __syncwarp();
    }

    // sum selected float32 costs
    double local = 0.0;
#pragma unroll
    for (int k = 0; k < KMAX; k++) {
        int j = 1 + lane + 32 * k;
        if (j <= QQ) {
            int pj = s_p[j];
            if (pj > 0) local += (double)C[pj - 1][j - 1];
        }
    }
#pragma unroll
    for (int off = 16; off > 0; off >>= 1)
        local += __shfl_down_sync(0xffffffffu, local, off);
    if (lane == 0) { g_l1[b] = local; g_cnt[b] = n; }
}

// ---------------- kernel 2: BCE + final combine ----------------
__global__ void final_kernel(const float* __restrict__ IVT,
                             const int* __restrict__ triplet,
                             float* __restrict__ out) {
    const int tid = threadIdx.x;
    __shared__ double r1[256], r2[256], r3[256];

    double l1 = 0.0, cnt = 0.0;
    for (int b = tid; b < BB; b += 256) { l1 += g_l1[b]; cnt += (double)g_cnt[b]; }

    double bce = 0.0;
    for (int i = tid; i < BB * 32; i += 256) {
        float x = IVT[i];
        float t = (float)triplet[i];
        float v = fmaxf(x, 0.f) - x * t + log1pf(expf(-fabsf(x)));
        bce += (double)(c_tw[i & 31] * v);
    }
    r1[tid] = l1; r2[tid] = cnt; r3[tid] = bce;
    __syncthreads();
    for (int s = 128; s > 0; s >>= 1) {
        if (tid < s) { r1[tid] += r1[tid + s]; r2[tid] += r2[tid + s]; r3[tid] += r3[tid + s]; }
        __syncthreads();
    }
    if (tid == 0) {
        double loss1 = r1[0] / r2[0];
        double loss5 = r3[0] / (double)(BB * 32);
        out[0] = (float)(0.1 * loss1 + 1.0 * loss5);
    }
}

// ---------------- launch ----------------
extern "C" void kernel_launch(void* const* d_in, const int* in_sizes, int n_in,
                              void* d_out, int out_size) {
    const float* pred_head = (const float*)d_in[0];
    const float* pred_rel  = (const float*)d_in[1];
    const float* pred_tail = (const float*)d_in[2];
    const float* IVT       = (const float*)d_in[3];
    const int*   iid       = (const int*)d_in[4];
    const int*   vid       = (const int*)d_in[5];
    const int*   tgt       = (const int*)d_in[6];
    // d_in[7..9] (instrument, verb, target) unused by the reference
    const int*   triplet   = (const int*)d_in[10];
    const int*   mask      = (const int*)d_in[11];
    float* out = (float*)d_out;

    fused_kernel<<<BB, 128>>>(pred_head, pred_rel, pred_tail, iid, vid, tgt, mask);
    final_kernel<<<1, 256>>>(IVT, triplet, out);
}

// round 7
// speedup vs baseline: 1.7740x; 1.1378x over previous
#include <cuda_runtime.h>
#include <math.h>

#define BB 256
#define QQ 300
#define GG 16
#define KMAX 10   // ceil(QQ/32) columns per lane

// ---------------- device scratch (no allocations allowed) ----------------
__device__ double g_l1[BB];               // per-batch selected-cost sum
__device__ double g_bce[BB];              // per-batch weighted BCE sum
__device__ int    g_cnt[BB];              // per-batch nval

__constant__ float c_tw[32] = {
    1.17236407f, 1.0166286f, 1.19620973f, 0.5544405f, 0.63531401f, 0.51258428f,
    1.08866652f, 1.15795989f, 1.07389395f, 0.98728399f, 1.12754142f, 1.05953744f,
    1.16945323f, 1.15512349f, 1.02097204f, 1.15795989f, 1.07147279f, 0.50627649f,
    1.07147279f, 0.61697221f, 1.16367678f, 1.0231585f, 1.18416106f, 1.04329092f,
    1.10645159f, 1.18416106f, 1.15795989f, 1.16367678f, 0.73949534f, 0.78760821f,
    1.08617476f, 1.00805777f
};

// ---- fused kernel: BCE (warp 1) + cost tile (all warps) + Hungarian (warp 0) ----
__global__ __launch_bounds__(128) void fused_kernel(
    const float* __restrict__ ph,
    const float* __restrict__ pr,
    const float* __restrict__ pt,
    const float* __restrict__ IVT,
    const int* __restrict__ iid,
    const int* __restrict__ vid,
    const int* __restrict__ tgt,
    const int* __restrict__ triplet,
    const int* __restrict__ mask)
{
    const int b   = blockIdx.x;
    const int tid = threadIdx.x;

    __shared__ float C[GG][QQ];           // cost[g][q], row-contiguous in q
    __shared__ float s_u[GG + 1];
    __shared__ int   s_p[QQ + 1];
    __shared__ int   s_way[QQ + 1];
    __shared__ int   si[GG], sv[GG], st[GG];

    // ---- phase 0: warp 1 computes this batch row's weighted BCE (overlapped) ----
    if (tid >= 32 && tid < 64) {
        const int l = tid - 32;
        float x = IVT[b * 32 + l];
        float t = (float)triplet[b * 32 + l];
        float v = fmaxf(x, 0.f) - x * t + log1pf(expf(-fabsf(x)));
        double s = (double)(c_tw[l] * v);
#pragma unroll
        for (int off = 16; off > 0; off >>= 1)
            s += __shfl_down_sync(0xffffffffu, s, off);
        if (l == 0) g_bce[b] = s;
    }

    if (tid < GG) {
        si[tid] = iid[b * GG + tid];
        sv[tid] = vid[b * GG + tid];
        st[tid] = tgt[b * GG + tid];
    }
    for (int j = tid; j <= QQ; j += 128) { s_p[j] = 0; s_way[j] = 0; }
    if (tid <= GG) s_u[tid] = 0.f;
    __syncthreads();

    // ---- phase 1: cost matrix into shared ----
    for (int q = tid; q < QQ; q += 128) {
        float h[9], r[13], t[2];
        const float* hp = ph + (size_t)(b * QQ + q) * 9;
        const float* rp = pr + (size_t)(b * QQ + q) * 13;
        const float* tp = pt + (size_t)(b * QQ + q) * 2;

        float mh = -INFINITY, mr = -INFINITY, mt = -INFINITY;
#pragma unroll
        for (int i = 0; i < 9; i++)  { h[i] = hp[i]; mh = fmaxf(mh, h[i]); }
#pragma unroll
        for (int i = 0; i < 13; i++) { r[i] = rp[i]; mr = fmaxf(mr, r[i]); }
#pragma unroll
        for (int i = 0; i < 2; i++)  { t[i] = tp[i]; mt = fmaxf(mt, t[i]); }

        float sh = 0.f, sr = 0.f, stt = 0.f;
#pragma unroll
        for (int i = 0; i < 9; i++)  sh  += expf(h[i] - mh);
#pragma unroll
        for (int i = 0; i < 13; i++) sr  += expf(r[i] - mr);
#pragma unroll
        for (int i = 0; i < 2; i++)  stt += expf(t[i] - mt);

        float lh = mh + logf(sh);
        float lr = mr + logf(sr);
        float lt = mt + logf(stt);

#pragma unroll
        for (int g = 0; g < GG; g++) {
            C[g][q] = (lh - h[si[g]]) + (lr - r[sv[g]]) + (lt - t[st[g]]);
        }
    }
    __syncthreads();

    // ---- phase 2: warp 0 runs JV Hungarian ----
    if (tid >= 32) return;
    const int lane = tid;

    unsigned mb = __ballot_sync(0xffffffffu, lane < GG && mask[b * GG + lane] != 0);
    const int n = __popc(mb);

    float v[KMAX], minv[KMAX];
#pragma unroll
    for (int k = 0; k < KMAX; k++) v[k] = 0.f;

    for (int i = 1; i <= n; i++) {
#pragma unroll
        for (int k = 0; k < KMAX; k++) minv[k] = INFINITY;
        unsigned used = 0;
        int j0 = 0;
        if (lane == 0) s_p[0] = i;
        __syncwarp();

        while (true) {
            if (j0 > 0 && (((j0 - 1) & 31) == lane))
                used |= 1u << ((j0 - 1) >> 5);

            const int   i0   = s_p[j0];
            const float u_i0 = s_u[i0];
            const float* Crow = &C[i0 - 1][0];

            float best = INFINITY;
            int   bidx = QQ + 2;
#pragma unroll
            for (int k = 0; k < KMAX; k++) {
                int j = 1 + lane + 32 * k;
                if (j <= QQ && !((used >> k) & 1u)) {
                    float cur = Crow[j - 1] - u_i0 - v[k];
                    if (cur < minv[k]) { minv[k] = cur; s_way[j] = j0; }
                    if (minv[k] < best) { best = minv[k]; bidx = j; }  // k ascending => lowest j wins ties
                }
            }
#pragma unroll
            for (int off = 16; off > 0; off >>= 1) {
                float ov = __shfl_down_sync(0xffffffffu, best, off);
                int   oi = __shfl_down_sync(0xffffffffu, bidx, off);
                if (ov < best || (ov == best && oi < bidx)) { best = ov; bidx = oi; }
            }
            const float delta = __shfl_sync(0xffffffffu, best, 0);
            const int   j1    = __shfl_sync(0xffffffffu, bidx, 0);

#pragma unroll
            for (int k = 0; k < KMAX; k++) {
                int j = 1 + lane + 32 * k;
                if (j <= QQ) {
                    if ((used >> k) & 1u) {
                        v[k] -= delta;
                        s_u[s_p[j]] += delta;     // distinct p[j] across used cols
                    } else {
                        minv[k] -= delta;
                    }
                }
            }
            if (lane == 0) s_u[i] += delta;       // virtual column 0 (p[0] = i)
            __syncwarp();

            if (s_p[j1] == 0) { j0 = j1; break; }
            j0 = j1;
        }

        if (lane == 0) {
            int jj = j0;
            while (jj) {
                int jp = s_way[jj];
                s_p[jj] = s_p[jp];
                jj = jp;
            }
        }
        __syncwarp();
    }

    // sum selected float32 costs
    double local = 0.0;
#pragma unroll
    for (int k = 0; k < KMAX; k++) {
        int j = 1 + lane + 32 * k;
        if (j <= QQ) {
            int pj = s_p[j];
            if (pj > 0) local += (double)C[pj - 1][j - 1];
        }
    }
#pragma unroll
    for (int off = 16; off > 0; off >>= 1)
        local += __shfl_down_sync(0xffffffffu, local, off);
    if (lane == 0) { g_l1[b] = local; g_cnt[b] = n; }
}

// ---------------- kernel 2: tiny combine (one warp, L2-hot data) ----------------
__global__ void combine_kernel(float* __restrict__ out) {
    const int lane = threadIdx.x;
    double l1 = 0.0, cnt = 0.0, bce = 0.0;
#pragma unroll
    for (int k = 0; k < BB / 32; k++) {
        int b = lane + 32 * k;
        l1  += g_l1[b];
        cnt += (double)g_cnt[b];
        bce += g_bce[b];
    }
#pragma unroll
    for (int off = 16; off > 0; off >>= 1) {
        l1  += __shfl_down_sync(0xffffffffu, l1, off);
        cnt += __shfl_down_sync(0xffffffffu, cnt, off);
        bce += __shfl_down_sync(0xffffffffu, bce, off);
    }
    if (lane == 0) {
        double loss1 = l1 / cnt;
        double loss5 = bce / (double)(BB * 32);
        out[0] = (float)(0.1 * loss1 + 1.0 * loss5);
    }
}

// ---------------- launch ----------------
extern "C" void kernel_launch(void* const* d_in, const int* in_sizes, int n_in,
                              void* d_out, int out_size) {
    const float* pred_head = (const float*)d_in[0];
    const float* pred_rel  = (const float*)d_in[1];
    const float* pred_tail = (const float*)d_in[2];
    const float* IVT       = (const float*)d_in[3];
    const int*   iid       = (const int*)d_in[4];
    const int*   vid       = (const int*)d_in[5];
    const int*   tgt       = (const int*)d_in[6];
    // d_in[7..9] (instrument, verb, target) unused by the reference
    const int*   triplet   = (const int*)d_in[10];
    const int*   mask      = (const int*)d_in[11];
    float* out = (float*)d_out;

    fused_kernel<<<BB, 128>>>(pred_head, pred_rel, pred_tail, IVT,
                              iid, vid, tgt, triplet, mask);
    combine_kernel<<<1, 32>>>(out);
}

// round 8
// speedup vs baseline: 1.8650x; 1.0513x over previous
#include <cuda_runtime.h>
#include <math.h>

#define BB 256
#define QQ 300
#define GG 16
#define KMAX 10   // ceil(QQ/32) columns per lane

// ---------------- device scratch (no allocations allowed) ----------------
__device__ double   g_l1[BB];             // per-batch selected-cost sum
__device__ double   g_bce[BB];            // per-batch weighted BCE sum
__device__ int      g_cnt[BB];            // per-batch nval
__device__ unsigned g_done = 0;           // done-counter (last block resets to 0)

__constant__ float c_tw[32] = {
    1.17236407f, 1.0166286f, 1.19620973f, 0.5544405f, 0.63531401f, 0.51258428f,
    1.08866652f, 1.15795989f, 1.07389395f, 0.98728399f, 1.12754142f, 1.05953744f,
    1.16945323f, 1.15512349f, 1.02097204f, 1.15795989f, 1.07147279f, 0.50627649f,
    1.07147279f, 0.61697221f, 1.16367678f, 1.0231585f, 1.18416106f, 1.04329092f,
    1.10645159f, 1.18416106f, 1.15795989f, 1.16367678f, 0.73949534f, 0.78760821f,
    1.08617476f, 1.00805777f
};

// order-preserving float <-> u32 key (finite + inf safe)
__device__ __forceinline__ unsigned f2key(float f) {
    unsigned u = __float_as_uint(f);
    return (u & 0x80000000u) ? ~u : (u | 0x80000000u);
}
__device__ __forceinline__ float key2f(unsigned k) {
    unsigned u = (k & 0x80000000u) ? (k & 0x7fffffffu) : ~k;
    return __uint_as_float(u);
}

// ---- fused kernel: BCE (warp 0) + cost tile (all warps) + Hungarian (warp 0)
//      + last-block final combine ----
__global__ __launch_bounds__(128) void fused_kernel(
    const float* __restrict__ ph,
    const float* __restrict__ pr,
    const float* __restrict__ pt,
    const float* __restrict__ IVT,
    const int* __restrict__ iid,
    const int* __restrict__ vid,
    const int* __restrict__ tgt,
    const int* __restrict__ triplet,
    const int* __restrict__ mask,
    float* __restrict__ out)
{
    const int b   = blockIdx.x;
    const int tid = threadIdx.x;

    __shared__ float C[GG][QQ];           // cost[g][q], row-contiguous in q
    __shared__ float s_u[GG + 1];
    __shared__ int   s_p[QQ + 1];
    __shared__ int   s_way[QQ + 1];
    __shared__ int   si[GG], sv[GG], st[GG];

    // ---- phase 0: warp 0 computes this batch row's weighted BCE (overlapped).
    // Done by warp 0 so the write is ordered by warp 0's later __threadfence().
    double bce_row = 0.0;
    if (tid < 32) {
        float x = IVT[b * 32 + tid];
        float t = (float)triplet[b * 32 + tid];
        float v = fmaxf(x, 0.f) - x * t + log1pf(expf(-fabsf(x)));
        bce_row = (double)(c_tw[tid] * v);
#pragma unroll
        for (int off = 16; off > 0; off >>= 1)
            bce_row += __shfl_down_sync(0xffffffffu, bce_row, off);
    }

    if (tid < GG) {
        si[tid] = iid[b * GG + tid];
        sv[tid] = vid[b * GG + tid];
        st[tid] = tgt[b * GG + tid];
    }
    for (int j = tid; j <= QQ; j += 128) { s_p[j] = 0; s_way[j] = 0; }
    if (tid <= GG) s_u[tid] = 0.f;
    __syncthreads();

    // ---- phase 1: cost matrix into shared ----
    for (int q = tid; q < QQ; q += 128) {
        float h[9], r[13], t[2];
        const float* hp = ph + (size_t)(b * QQ + q) * 9;
        const float* rp = pr + (size_t)(b * QQ + q) * 13;
        const float* tp = pt + (size_t)(b * QQ + q) * 2;

        float mh = -INFINITY, mr = -INFINITY, mt = -INFINITY;
#pragma unroll
        for (int i = 0; i < 9; i++)  { h[i] = hp[i]; mh = fmaxf(mh, h[i]); }
#pragma unroll
        for (int i = 0; i < 13; i++) { r[i] = rp[i]; mr = fmaxf(mr, r[i]); }
#pragma unroll
        for (int i = 0; i < 2; i++)  { t[i] = tp[i]; mt = fmaxf(mt, t[i]); }

        float sh = 0.f, sr = 0.f, stt = 0.f;
#pragma unroll
        for (int i = 0; i < 9; i++)  sh  += expf(h[i] - mh);
#pragma unroll
        for (int i = 0; i < 13; i++) sr  += expf(r[i] - mr);
#pragma unroll
        for (int i = 0; i < 2; i++)  stt += expf(t[i] - mt);

        float lh = mh + logf(sh);
        float lr = mr + logf(sr);
        float lt = mt + logf(stt);

#pragma unroll
        for (int g = 0; g < GG; g++) {
            C[g][q] = (lh - h[si[g]]) + (lr - r[sv[g]]) + (lt - t[st[g]]);
        }
    }
    __syncthreads();

    // ---- phase 2: warp 0 runs JV Hungarian ----
    if (tid >= 32) return;
    const int lane = tid;

    unsigned mb = __ballot_sync(0xffffffffu, lane < GG && mask[b * GG + lane] != 0);
    const int n = __popc(mb);

    float v[KMAX], minv[KMAX];
#pragma unroll
    for (int k = 0; k < KMAX; k++) v[k] = 0.f;

    for (int i = 1; i <= n; i++) {
#pragma unroll
        for (int k = 0; k < KMAX; k++) minv[k] = INFINITY;
        unsigned used = 0;
        int j0 = 0;
        if (lane == 0) s_p[0] = i;
        __syncwarp();

        while (true) {
            if (j0 > 0 && (((j0 - 1) & 31) == lane))
                used |= 1u << ((j0 - 1) >> 5);

            const int   i0   = s_p[j0];
            const float u_i0 = s_u[i0];
            const float* Crow = &C[i0 - 1][0];

            float best = INFINITY;
            int   bidx = QQ + 2;
#pragma unroll
            for (int k = 0; k < KMAX; k++) {
                int j = 1 + lane + 32 * k;
                if (j <= QQ && !((used >> k) & 1u)) {
                    float cur = Crow[j - 1] - u_i0 - v[k];
                    if (cur < minv[k]) { minv[k] = cur; s_way[j] = j0; }
                    if (minv[k] < best) { best = minv[k]; bidx = j; }  // k ascending => lowest j wins ties
                }
            }
            // hardware warp argmin: value via order-preserving key, then lowest-j tie-break
            const unsigned mykey = f2key(best);
            const unsigned mkey  = __reduce_min_sync(0xffffffffu, mykey);
            const unsigned cand  = (mykey == mkey) ? (unsigned)bidx : 0xffffffffu;
            const int      j1    = (int)__reduce_min_sync(0xffffffffu, cand);
            const float    delta = key2f(mkey);

#pragma unroll
            for (int k = 0; k < KMAX; k++) {
                int j = 1 + lane + 32 * k;
                if (j <= QQ) {
                    if ((used >> k) & 1u) {
                        v[k] -= delta;
                        s_u[s_p[j]] += delta;     // distinct p[j] across used cols
                    } else {
                        minv[k] -= delta;
                    }
                }
            }
            if (lane == 0) s_u[i] += delta;       // virtual column 0 (p[0] = i)
            __syncwarp();

            if (s_p[j1] == 0) { j0 = j1; break; }
            j0 = j1;
        }

        if (lane == 0) {
            int jj = j0;
            while (jj) {
                int jp = s_way[jj];
                s_p[jj] = s_p[jp];
                jj = jp;
            }
        }
        __syncwarp();
    }

    // sum selected float32 costs
    double local = 0.0;
#pragma unroll
    for (int k = 0; k < KMAX; k++) {
        int j = 1 + lane + 32 * k;
        if (j <= QQ) {
            int pj = s_p[j];
            if (pj > 0) local += (double)C[pj - 1][j - 1];
        }
    }
#pragma unroll
    for (int off = 16; off > 0; off >>= 1)
        local += __shfl_down_sync(0xffffffffu, local, off);
    if (lane == 0) {
        g_l1[b]  = local;
        g_cnt[b] = n;
        g_bce[b] = bce_row;
    }

    // ---- phase 3: last block performs the final combine (deterministic order) ----
    __threadfence();
    unsigned old = 0;
    if (lane == 0) old = atomicAdd(&g_done, 1u);
    old = __shfl_sync(0xffffffffu, old, 0);
    if (old == BB - 1) {
        double l1 = 0.0, cnt = 0.0, bce = 0.0;
#pragma unroll
        for (int k = 0; k < BB / 32; k++) {
            int bb = lane + 32 * k;
            l1  += __ldcg(&g_l1[bb]);
            cnt += (double)__ldcg(&g_cnt[bb]);
            bce += __ldcg(&g_bce[bb]);
        }
#pragma unroll
        for (int off = 16; off > 0; off >>= 1) {
            l1  += __shfl_down_sync(0xffffffffu, l1, off);
            cnt += __shfl_down_sync(0xffffffffu, cnt, off);
            bce += __shfl_down_sync(0xffffffffu, bce, off);
        }
        if (lane == 0) {
            double loss1 = l1 / cnt;
            double loss5 = bce / (double)(BB * 32);
            out[0] = (float)(0.1 * loss1 + 1.0 * loss5);
            g_done = 0;                      // reset for next graph replay
        }
    }
}

// ---------------- launch ----------------
extern "C" void kernel_launch(void* const* d_in, const int* in_sizes, int n_in,
                              void* d_out, int out_size) {
    const float* pred_head = (const float*)d_in[0];
    const float* pred_rel  = (const float*)d_in[1];
    const float* pred_tail = (const float*)d_in[2];
    const float* IVT       = (const float*)d_in[3];
    const int*   iid       = (const int*)d_in[4];
    const int*   vid       = (const int*)d_in[5];
    const int*   tgt       = (const int*)d_in[6];
    // d_in[7..9] (instrument, verb, target) unused by the reference
    const int*   triplet   = (const int*)d_in[10];
    const int*   mask      = (const int*)d_in[11];
    float* out = (float*)d_out;

    fused_kernel<<<BB, 128>>>(pred_head, pred_rel, pred_tail, IVT,
                              iid, vid, tgt, triplet, mask, out);
}

// round 9
// speedup vs baseline: 2.6195x; 1.4046x over previous
#include <cuda_runtime.h>
#include <math.h>

#define BB 256
#define QQ 300
#define GG 16
#define KMAX 10   // ceil(QQ/32) columns per lane

// ---------------- device scratch (no allocations allowed) ----------------
__device__ double   g_l1[BB];             // per-batch selected-cost sum
__device__ double   g_bce[BB];            // per-batch weighted BCE sum
__device__ int      g_cnt[BB];            // per-batch nval
__device__ unsigned g_done = 0;           // done-counter (last block resets to 0)

__constant__ float c_tw[32] = {
    1.17236407f, 1.0166286f, 1.19620973f, 0.5544405f, 0.63531401f, 0.51258428f,
    1.08866652f, 1.15795989f, 1.07389395f, 0.98728399f, 1.12754142f, 1.05953744f,
    1.16945323f, 1.15512349f, 1.02097204f, 1.15795989f, 1.07147279f, 0.50627649f,
    1.07147279f, 0.61697221f, 1.16367678f, 1.0231585f, 1.18416106f, 1.04329092f,
    1.10645159f, 1.18416106f, 1.15795989f, 1.16367678f, 0.73949534f, 0.78760821f,
    1.08617476f, 1.00805777f
};

// order-preserving float <-> u32 key (finite + inf safe)
__device__ __forceinline__ unsigned f2key(float f) {
    unsigned u = __float_as_uint(f);
    return (u & 0x80000000u) ? ~u : (u | 0x80000000u);
}
__device__ __forceinline__ float key2f(unsigned k) {
    unsigned u = (k & 0x80000000u) ? (k & 0x7fffffffu) : ~k;
    return __uint_as_float(u);
}

// warp argmin (value, lowest index among minima)
__device__ __forceinline__ void warp_argmin(float val, int idx, float& mval, int& midx) {
    const unsigned mykey = f2key(val);
    const unsigned mkey  = __reduce_min_sync(0xffffffffu, mykey);
    const unsigned cand  = (mykey == mkey) ? (unsigned)idx : 0xffffffffu;
    midx = (int)__reduce_min_sync(0xffffffffu, cand);
    mval = key2f(mkey);
}

// ---- fused kernel: BCE (warp 0) + cost tile (all warps) + LAP (warp 0)
//      + last-block final combine ----
__global__ __launch_bounds__(128) void fused_kernel(
    const float* __restrict__ ph,
    const float* __restrict__ pr,
    const float* __restrict__ pt,
    const float* __restrict__ IVT,
    const int* __restrict__ iid,
    const int* __restrict__ vid,
    const int* __restrict__ tgt,
    const int* __restrict__ triplet,
    const int* __restrict__ mask,
    float* __restrict__ out)
{
    const int b   = blockIdx.x;
    const int tid = threadIdx.x;

    __shared__ float C[GG][QQ];           // cost[g][q], row-contiguous in q
    __shared__ float s_u[GG + 1];
    __shared__ int   s_p[QQ + 1];
    __shared__ int   s_way[QQ + 1];
    __shared__ int   si[GG], sv[GG], st[GG];
    __shared__ int   s_unass[GG];         // rows left unassigned by greedy init

    // ---- phase 0: warp 0 computes this batch row's weighted BCE (overlapped).
    double bce_row = 0.0;
    if (tid < 32) {
        float x = IVT[b * 32 + tid];
        float t = (float)triplet[b * 32 + tid];
        float v = fmaxf(x, 0.f) - x * t + log1pf(expf(-fabsf(x)));
        bce_row = (double)(c_tw[tid] * v);
#pragma unroll
        for (int off = 16; off > 0; off >>= 1)
            bce_row += __shfl_down_sync(0xffffffffu, bce_row, off);
    }

    if (tid < GG) {
        si[tid] = iid[b * GG + tid];
        sv[tid] = vid[b * GG + tid];
        st[tid] = tgt[b * GG + tid];
    }
    for (int j = tid; j <= QQ; j += 128) { s_p[j] = 0; s_way[j] = 0; }
    if (tid <= GG) s_u[tid] = 0.f;
    __syncthreads();

    // ---- phase 1: cost matrix into shared ----
    for (int q = tid; q < QQ; q += 128) {
        float h[9], r[13], t[2];
        const float* hp = ph + (size_t)(b * QQ + q) * 9;
        const float* rp = pr + (size_t)(b * QQ + q) * 13;
        const float* tp = pt + (size_t)(b * QQ + q) * 2;

        float mh = -INFINITY, mr = -INFINITY, mt = -INFINITY;
#pragma unroll
        for (int i = 0; i < 9; i++)  { h[i] = hp[i]; mh = fmaxf(mh, h[i]); }
#pragma unroll
        for (int i = 0; i < 13; i++) { r[i] = rp[i]; mr = fmaxf(mr, r[i]); }
#pragma unroll
        for (int i = 0; i < 2; i++)  { t[i] = tp[i]; mt = fmaxf(mt, t[i]); }

        float sh = 0.f, sr = 0.f, stt = 0.f;
#pragma unroll
        for (int i = 0; i < 9; i++)  sh  += expf(h[i] - mh);
#pragma unroll
        for (int i = 0; i < 13; i++) sr  += expf(r[i] - mr);
#pragma unroll
        for (int i = 0; i < 2; i++)  stt += expf(t[i] - mt);

        float lh = mh + logf(sh);
        float lr = mr + logf(sr);
        float lt = mt + logf(stt);

#pragma unroll
        for (int g = 0; g < GG; g++) {
            C[g][q] = (lh - h[si[g]]) + (lr - r[sv[g]]) + (lt - t[st[g]]);
        }
    }
    __syncthreads();

    // ---- phase 2: warp 0 solves the LAP ----
    if (tid >= 32) return;
    const int lane = tid;

    unsigned mb = __ballot_sync(0xffffffffu, lane < GG && mask[b * GG + lane] != 0);
    const int n = __popc(mb);

    float v[KMAX], minv[KMAX];
#pragma unroll
    for (int k = 0; k < KMAX; k++) v[k] = 0.f;

    // -- phase 2a: greedy row-min initialization --
    // u[i] = min_j C[i][j]; assign row i to its argmin column if still free.
    // This is a feasible JV state (reduced costs >= 0, matched edges tight),
    // so Dijkstra below only runs for collided rows.
    int n_unass = 0;
    for (int i = 1; i <= n; i++) {
        const float* Crow = &C[i - 1][0];
        float best = INFINITY;
        int   bidx = QQ + 2;
#pragma unroll
        for (int k = 0; k < KMAX; k++) {
            int j = 1 + lane + 32 * k;
            if (j <= QQ) {
                float c = Crow[j - 1];
                if (c < best) { best = c; bidx = j; }
            }
        }
        float rmin; int jm;
        warp_argmin(best, bidx, rmin, jm);
        if (lane == 0) {
            s_u[i] = rmin;
            if (s_p[jm] == 0) s_p[jm] = i;
            else              s_unass[n_unass++] = i;
        }
        n_unass = __shfl_sync(0xffffffffu, n_unass, 0);
    }
    __syncwarp();

    // -- phase 2b: Dijkstra augmentation for unassigned rows only --
    for (int ui = 0; ui < n_unass; ui++) {
        const int i = s_unass[ui];
#pragma unroll
        for (int k = 0; k < KMAX; k++) minv[k] = INFINITY;
        unsigned used = 0;
        int j0 = 0;
        if (lane == 0) s_p[0] = i;
        __syncwarp();

        while (true) {
            if (j0 > 0 && (((j0 - 1) & 31) == lane))
                used |= 1u << ((j0 - 1) >> 5);

            const int   i0   = s_p[j0];
            const float u_i0 = s_u[i0];
            const float* Crow = &C[i0 - 1][0];

            float best = INFINITY;
            int   bidx = QQ + 2;
#pragma unroll
            for (int k = 0; k < KMAX; k++) {
                int j = 1 + lane + 32 * k;
                if (j <= QQ && !((used >> k) & 1u)) {
                    float cur = Crow[j - 1] - u_i0 - v[k];
                    if (cur < minv[k]) { minv[k] = cur; s_way[j] = j0; }
                    if (minv[k] < best) { best = minv[k]; bidx = j; }
                }
            }
            float delta; int j1;
            warp_argmin(best, bidx, delta, j1);

#pragma unroll
            for (int k = 0; k < KMAX; k++) {
                int j = 1 + lane + 32 * k;
                if (j <= QQ) {
                    if ((used >> k) & 1u) {
                        v[k] -= delta;
                        s_u[s_p[j]] += delta;     // distinct p[j] across used cols
                    } else {
                        minv[k] -= delta;
                    }
                }
            }
            if (lane == 0) s_u[i] += delta;       // virtual column 0 (p[0] = i)
            __syncwarp();

            if (s_p[j1] == 0) { j0 = j1; break; }
            j0 = j1;
        }

        // augment alternating path
        if (lane == 0) {
            int jj = j0;
            while (jj) {
                int jp = s_way[jj];
                s_p[jj] = s_p[jp];
                jj = jp;
            }
        }
        __syncwarp();
    }

    // sum selected float32 costs (optimal total is assignment-independent)
    double local = 0.0;
#pragma unroll
    for (int k = 0; k < KMAX; k++) {
        int j = 1 + lane + 32 * k;
        if (j <= QQ) {
            int pj = s_p[j];
            if (pj > 0) local += (double)C[pj - 1][j - 1];
        }
    }
#pragma unroll
    for (int off = 16; off > 0; off >>= 1)
        local += __shfl_down_sync(0xffffffffu, local, off);
    if (lane == 0) {
        g_l1[b]  = local;
        g_cnt[b] = n;
        g_bce[b] = bce_row;
    }

    // ---- phase 3: last block performs the final combine (deterministic order) ----
    __threadfence();
    unsigned old = 0;
    if (lane == 0) old = atomicAdd(&g_done, 1u);
    old = __shfl_sync(0xffffffffu, old, 0);
    if (old == BB - 1) {
        double l1 = 0.0, cnt = 0.0, bce = 0.0;
#pragma unroll
        for (int k = 0; k < BB / 32; k++) {
            int bb = lane + 32 * k;
            l1  += __ldcg(&g_l1[bb]);
            cnt += (double)__ldcg(&g_cnt[bb]);
            bce += __ldcg(&g_bce[bb]);
        }
#pragma unroll
        for (int off = 16; off > 0; off >>= 1) {
            l1  += __shfl_down_sync(0xffffffffu, l1, off);
            cnt += __shfl_down_sync(0xffffffffu, cnt, off);
            bce += __shfl_down_sync(0xffffffffu, bce, off);
        }
        if (lane == 0) {
            double loss1 = l1 / cnt;
            double loss5 = bce / (double)(BB * 32);
            out[0] = (float)(0.1 * loss1 + 1.0 * loss5);
            g_done = 0;                      // reset for next graph replay
        }
    }
}

// ---------------- launch ----------------
extern "C" void kernel_launch(void* const* d_in, const int* in_sizes, int n_in,
                              void* d_out, int out_size) {
    const float* pred_head = (const float*)d_in[0];
    const float* pred_rel  = (const float*)d_in[1];
    const float* pred_tail = (const float*)d_in[2];
    const float* IVT       = (const float*)d_in[3];
    const int*   iid       = (const int*)d_in[4];
    const int*   vid       = (const int*)d_in[5];
    const int*   tgt       = (const int*)d_in[6];
    // d_in[7..9] (instrument, verb, target) unused by the reference
    const int*   triplet   = (const int*)d_in[10];
    const int*   mask      = (const int*)d_in[11];
    float* out = (float*)d_out;

    fused_kernel<<<BB, 128>>>(pred_head, pred_rel, pred_tail, IVT,
                              iid, vid, tgt, triplet, mask, out);
}

// round 10
// speedup vs baseline: 2.8462x; 1.0865x over previous
#include <cuda_runtime.h>
#include <math.h>

#define BB 256
#define QQ 300
#define GG 16
#define KMAX 10   // ceil(QQ/32) columns per lane
#define NTHR 320  // one q per thread in phase 1; 10 warps

// ---------------- device scratch (no allocations allowed) ----------------
__device__ double   g_l1[BB];             // per-batch selected-cost sum
__device__ double   g_bce[BB];            // per-batch weighted BCE sum
__device__ int      g_cnt[BB];            // per-batch nval
__device__ unsigned g_done = 0;           // done-counter (last block resets to 0)

__constant__ float c_tw[32] = {
    1.17236407f, 1.0166286f, 1.19620973f, 0.5544405f, 0.63531401f, 0.51258428f,
    1.08866652f, 1.15795989f, 1.07389395f, 0.98728399f, 1.12754142f, 1.05953744f,
    1.16945323f, 1.15512349f, 1.02097204f, 1.15795989f, 1.07147279f, 0.50627649f,
    1.07147279f, 0.61697221f, 1.16367678f, 1.0231585f, 1.18416106f, 1.04329092f,
    1.10645159f, 1.18416106f, 1.15795989f, 1.16367678f, 0.73949534f, 0.78760821f,
    1.08617476f, 1.00805777f
};

// order-preserving float <-> u32 key (finite + inf safe)
__device__ __forceinline__ unsigned f2key(float f) {
    unsigned u = __float_as_uint(f);
    return (u & 0x80000000u) ? ~u : (u | 0x80000000u);
}
__device__ __forceinline__ float key2f(unsigned k) {
    unsigned u = (k & 0x80000000u) ? (k & 0x7fffffffu) : ~k;
    return __uint_as_float(u);
}

// warp argmin (value, lowest index among minima)
__device__ __forceinline__ void warp_argmin(float val, int idx, float& mval, int& midx) {
    const unsigned mykey = f2key(val);
    const unsigned mkey  = __reduce_min_sync(0xffffffffu, mykey);
    const unsigned cand  = (mykey == mkey) ? (unsigned)idx : 0xffffffffu;
    midx = (int)__reduce_min_sync(0xffffffffu, cand);
    mval = key2f(mkey);
}

// ---- fused kernel ----
__global__ __launch_bounds__(NTHR) void fused_kernel(
    const float* __restrict__ ph,
    const float* __restrict__ pr,
    const float* __restrict__ pt,
    const float* __restrict__ IVT,
    const int* __restrict__ iid,
    const int* __restrict__ vid,
    const int* __restrict__ tgt,
    const int* __restrict__ triplet,
    const int* __restrict__ mask,
    float* __restrict__ out)
{
    const int b   = blockIdx.x;
    const int tid = threadIdx.x;
    const int wid = tid >> 5;

    __shared__ float C[GG][QQ];           // cost[g][q], row-contiguous in q
    __shared__ float s_u[GG + 1];
    __shared__ int   s_p[QQ + 1];
    __shared__ int   s_way[QQ + 1];
    __shared__ int   si[GG], sv[GG], st[GG];
    __shared__ int   s_unass[GG];         // rows left unassigned by greedy init
    __shared__ float s_rmin[GG];          // per-row min (parallel precompute)
    __shared__ int   s_jm[GG];            // per-row argmin column (1-based)

    // ---- phase 0: warp 0 computes this batch row's weighted BCE (overlapped).
    double bce_row = 0.0;
    if (tid < 32) {
        float x = IVT[b * 32 + tid];
        float t = (float)triplet[b * 32 + tid];
        float v = fmaxf(x, 0.f) - x * t + log1pf(expf(-fabsf(x)));
        bce_row = (double)(c_tw[tid] * v);
#pragma unroll
        for (int off = 16; off > 0; off >>= 1)
            bce_row += __shfl_down_sync(0xffffffffu, bce_row, off);
    }

    if (tid < GG) {
        si[tid] = iid[b * GG + tid];
        sv[tid] = vid[b * GG + tid];
        st[tid] = tgt[b * GG + tid];
    }
    for (int j = tid; j <= QQ; j += NTHR) { s_p[j] = 0; s_way[j] = 0; }
    if (tid <= GG) s_u[tid] = 0.f;
    __syncthreads();

    // ---- phase 1: cost matrix into shared (one q per thread) ----
    if (tid < QQ) {
        const int q = tid;
        float h[9], r[13], t[2];
        const float* hp = ph + (size_t)(b * QQ + q) * 9;
        const float* rp = pr + (size_t)(b * QQ + q) * 13;
        const float* tp = pt + (size_t)(b * QQ + q) * 2;

        float mh = -INFINITY, mr = -INFINITY, mt = -INFINITY;
#pragma unroll
        for (int i = 0; i < 9; i++)  { h[i] = hp[i]; mh = fmaxf(mh, h[i]); }
#pragma unroll
        for (int i = 0; i < 13; i++) { r[i] = rp[i]; mr = fmaxf(mr, r[i]); }
#pragma unroll
        for (int i = 0; i < 2; i++)  { t[i] = tp[i]; mt = fmaxf(mt, t[i]); }

        float sh = 0.f, sr = 0.f, stt = 0.f;
#pragma unroll
        for (int i = 0; i < 9; i++)  sh  += expf(h[i] - mh);
#pragma unroll
        for (int i = 0; i < 13; i++) sr  += expf(r[i] - mr);
#pragma unroll
        for (int i = 0; i < 2; i++)  stt += expf(t[i] - mt);

        float lh = mh + logf(sh);
        float lr = mr + logf(sr);
        float lt = mt + logf(stt);

#pragma unroll
        for (int g = 0; g < GG; g++) {
            C[g][q] = (lh - h[si[g]]) + (lr - r[sv[g]]) + (lt - t[st[g]]);
        }
    }
    __syncthreads();

    // ---- phase 1b: all 10 warps compute row minima in parallel ----
    {
        const int lane = tid & 31;
#pragma unroll
        for (int rr = 0; rr < 2; rr++) {
            const int row = wid + 10 * rr;      // rows 0..15 covered by warps 0..9
            if (row < GG) {
                const float* Crow = &C[row][0];
                float best = INFINITY;
                int   bidx = QQ + 2;
#pragma unroll
                for (int k = 0; k < KMAX; k++) {
                    int j = 1 + lane + 32 * k;
                    if (j <= QQ) {
                        float c = Crow[j - 1];
                        if (c < best) { best = c; bidx = j; }
                    }
                }
                float rmin; int jm;
                warp_argmin(best, bidx, rmin, jm);
                if (lane == 0) { s_rmin[row] = rmin; s_jm[row] = jm; }
            }
        }
    }
    __syncthreads();

    // ---- phase 2: warp 0 solves the LAP ----
    if (tid >= 32) return;
    const int lane = tid;

    unsigned mb = __ballot_sync(0xffffffffu, lane < GG && mask[b * GG + lane] != 0);
    const int n = __popc(mb);

    float v[KMAX], minv[KMAX];
#pragma unroll
    for (int k = 0; k < KMAX; k++) v[k] = 0.f;

    // -- phase 2a: greedy init from precomputed row minima (serial but trivial) --
    int n_unass = 0;
    if (lane == 0) {
        for (int i = 1; i <= n; i++) {
            s_u[i] = s_rmin[i - 1];
            int jm = s_jm[i - 1];
            if (s_p[jm] == 0) s_p[jm] = i;
            else              s_unass[n_unass++] = i;
        }
    }
    n_unass = __shfl_sync(0xffffffffu, n_unass, 0);
    __syncwarp();

    // -- phase 2b: Dijkstra augmentation for unassigned rows only --
    for (int ui = 0; ui < n_unass; ui++) {
        const int i = s_unass[ui];
#pragma unroll
        for (int k = 0; k < KMAX; k++) minv[k] = INFINITY;
        unsigned used = 0;
        int j0 = 0;
        if (lane == 0) s_p[0] = i;
        __syncwarp();

        while (true) {
            if (j0 > 0 && (((j0 - 1) & 31) == lane))
                used |= 1u << ((j0 - 1) >> 5);

            const int   i0   = s_p[j0];
            const float u_i0 = s_u[i0];
            const float* Crow = &C[i0 - 1][0];

            float best = INFINITY;
            int   bidx = QQ + 2;
#pragma unroll
            for (int k = 0; k < KMAX; k++) {
                int j = 1 + lane + 32 * k;
                if (j <= QQ && !((used >> k) & 1u)) {
                    float cur = Crow[j - 1] - u_i0 - v[k];
                    if (cur < minv[k]) { minv[k] = cur; s_way[j] = j0; }
                    if (minv[k] < best) { best = minv[k]; bidx = j; }
                }
            }
            float delta; int j1;
            warp_argmin(best, bidx, delta, j1);

#pragma unroll
            for (int k = 0; k < KMAX; k++) {
                int j = 1 + lane + 32 * k;
                if (j <= QQ) {
                    if ((used >> k) & 1u) {
                        v[k] -= delta;
                        s_u[s_p[j]] += delta;     // distinct p[j] across used cols
                    } else {
                        minv[k] -= delta;
                    }
                }
            }
            if (lane == 0) s_u[i] += delta;       // virtual column 0 (p[0] = i)
            __syncwarp();

            if (s_p[j1] == 0) { j0 = j1; break; }
            j0 = j1;
        }

        // augment alternating path
        if (lane == 0) {
            int jj = j0;
            while (jj) {
                int jp = s_way[jj];
                s_p[jj] = s_p[jp];
                jj = jp;
            }
        }
        __syncwarp();
    }

    // sum selected float32 costs (optimal total is assignment-independent)
    double local = 0.0;
#pragma unroll
    for (int k = 0; k < KMAX; k++) {
        int j = 1 + lane + 32 * k;
        if (j <= QQ) {
            int pj = s_p[j];
            if (pj > 0) local += (double)C[pj - 1][j - 1];
        }
    }
#pragma unroll
    for (int off = 16; off > 0; off >>= 1)
        local += __shfl_down_sync(0xffffffffu, local, off);
    if (lane == 0) {
        g_l1[b]  = local;
        g_cnt[b] = n;
        g_bce[b] = bce_row;
    }

    // ---- phase 3: last block performs the final combine (deterministic order) ----
    __threadfence();
    unsigned old = 0;
    if (lane == 0) old = atomicAdd(&g_done, 1u);
    old = __shfl_sync(0xffffffffu, old, 0);
    if (old == BB - 1) {
        double l1 = 0.0, cnt = 0.0, bce = 0.0;
#pragma unroll
        for (int k = 0; k < BB / 32; k++) {
            int bb = lane + 32 * k;
            l1  += __ldcg(&g_l1[bb]);
            cnt += (double)__ldcg(&g_cnt[bb]);
            bce += __ldcg(&g_bce[bb]);
        }
#pragma unroll
        for (int off = 16; off > 0; off >>= 1) {
            l1  += __shfl_down_sync(0xffffffffu, l1, off);
            cnt += __shfl_down_sync(0xffffffffu, cnt, off);
            bce += __shfl_down_sync(0xffffffffu, bce, off);
        }
        if (lane == 0) {
            double loss1 = l1 / cnt;
            double loss5 = bce / (double)(BB * 32);
            out[0] = (float)(0.1 * loss1 + 1.0 * loss5);
            g_done = 0;                      // reset for next graph replay
        }
    }
}

// ---------------- launch ----------------
extern "C" void kernel_launch(void* const* d_in, const int* in_sizes, int n_in,
                              void* d_out, int out_size) {
    const float* pred_head = (const float*)d_in[0];
    const float* pred_rel  = (const float*)d_in[1];
    const float* pred_tail = (const float*)d_in[2];
    const float* IVT       = (const float*)d_in[3];
    const int*   iid       = (const int*)d_in[4];
    const int*   vid       = (const int*)d_in[5];
    const int*   tgt       = (const int*)d_in[6];
    // d_in[7..9] (instrument, verb, target) unused by the reference
    const int*   triplet   = (const int*)d_in[10];
    const int*   mask      = (const int*)d_in[11];
    float* out = (float*)d_out;

    fused_kernel<<<BB, NTHR>>>(pred_head, pred_rel, pred_tail, IVT,
                               iid, vid, tgt, triplet, mask, out);
}